// round 7
// baseline (speedup 1.0000x reference)
#include <cuda_runtime.h>
#include <cstdint>
#include <cstddef>

#define LEN 128
#define HID 64
#define NB 256
#define NN 2048
#define NROWS (NB*NN)          /* 524288 */
#define TILE_M 128
#define NTILES (NROWS/TILE_M)  /* 4096, 16 tiles per batch */
#define NEG_FILL -1.0e9f
#define LN_EPS 1e-3f
#define NTHREADS 512

/* plane-packed layouts: [plane p = k%4][row/col][j = k/4], conflict-free:
   row stride ≡ 4 (mod 32 floats), plane stride ≡ 8 (mod 32 floats) */
#define CST 36                 /* W col stride (floats) */
#define PST (128*CST + 8)      /* 4616 W plane stride */
#define WP_FLOATS (4*PST)      /* 18464 */
#define XJ 36                  /* X row stride within plane (floats) */
#define PXT (128*XJ + 8)       /* 4616 X plane stride */
#define XBUF (4*PXT)           /* 18464 floats per X buffer */

/* shared memory layout (floats) */
#define SM_W    0
#define SM_CG   WP_FLOATS
#define SM_CB   (SM_CG + 128)
#define SM_CC   (SM_CB + 128)
#define SM_X0   (SM_CC + 128)
#define SM_X1   (SM_X0 + XBUF)
#define SM_ST   (SM_X1 + XBUF)
#define SM_FLAG (SM_ST + TILE_M*8)
#define SM_FLOATS (SM_FLAG + 4)
#define SMEM_BYTES (SM_FLOATS*4)   /* ~227.3 KB */

__device__ float    g_Wp[WP_FLOATS];   /* combined W1@W2, tf32-rounded, plane-packed */
__device__ float    g_bc[LEN];         /* combined bias b1@W2 + b2 */
__device__ unsigned g_pool[NB*LEN];    /* per-(batch,channel) max, ordered-uint */
__device__ unsigned g_cnt[NB];         /* per-batch completed-tile counters */
__device__ int      g_mask_u8;

__device__ __forceinline__ unsigned f2o(float f){
  unsigned u = __float_as_uint(f);
  return (u & 0x80000000u) ? ~u : (u | 0x80000000u);
}
__device__ __forceinline__ float o2f(unsigned o){
  unsigned u = (o & 0x80000000u) ? (o & 0x7fffffffu) : ~o;
  return __uint_as_float(u);
}
__device__ __forceinline__ unsigned tf32r(float x){
  unsigned r; asm("cvt.rna.tf32.f32 %0, %1;" : "=r"(r) : "f"(x)); return r;
}
__device__ __forceinline__ void mma8(float* c, unsigned a0, unsigned a1, unsigned a2,
                                     unsigned a3, unsigned b0, unsigned b1){
  asm volatile(
    "mma.sync.aligned.m16n8k8.row.col.f32.tf32.tf32.f32 "
    "{%0,%1,%2,%3}, {%4,%5,%6,%7}, {%8,%9}, {%0,%1,%2,%3};\n"
    : "+f"(c[0]), "+f"(c[1]), "+f"(c[2]), "+f"(c[3])
    : "r"(a0), "r"(a1), "r"(a2), "r"(a3), "r"(b0), "r"(b1));
}
__device__ __forceinline__ void cpa4(float* s, const float* g){
  unsigned sa = (unsigned)__cvta_generic_to_shared(s);
  asm volatile("cp.async.ca.shared.global [%0], [%1], 4;\n" :: "r"(sa), "l"(g));
}

/* stage one 128x128 X tile into plane-packed smem buffer (32 x 4B cp.async/thread) */
__device__ __forceinline__ void stage_tile(float* dst, const float* __restrict__ src,
                                           int tid){
  /* idx = it*512 + tid; row = idx>>7; k = idx&127
     smem: (k&3)*PXT + row*XJ + (k>>2)  — all 32 banks hit once per warp op */
  #pragma unroll
  for (int it = 0; it < 32; it++){
    int idx = it*NTHREADS + tid;
    int row = idx >> 7, k = idx & 127;
    cpa4(dst + (k&3)*PXT + row*XJ + (k>>2), src + idx);
  }
}

/* ---- prep: combined weight (plane layout) + bias + pool/counter init + mask probe ---- */
__global__ void prep_kernel(const float* __restrict__ W1, const float* __restrict__ b1,
                            const float* __restrict__ W2, const float* __restrict__ b2,
                            const unsigned* __restrict__ mw){
  if (blockIdx.x == 0){
    __shared__ int flag;
    if (threadIdx.x == 0) flag = 0;
    __syncthreads();
    int loc = 0;
    #pragma unroll
    for (int k = 0; k < 4; k++)
      if (mw[threadIdx.x*4 + k] > 1u) loc = 1;   /* u8-packed bools -> words >1 */
    if (loc) flag = 1;
    __syncthreads();
    if (threadIdx.x == 0) g_mask_u8 = flag;
  }
  int i = blockIdx.x*blockDim.x + threadIdx.x;
  if (i < LEN*LEN){
    int k = i >> 7, c = i & 127;
    float s = 0.f;
    #pragma unroll
    for (int h = 0; h < HID; h++) s += W1[k*HID + h] * W2[h*LEN + c];
    g_Wp[(k&3)*PST + c*CST + (k>>2)] = __uint_as_float(tf32r(s));
  } else if (i < LEN*LEN + LEN){
    int c = i - LEN*LEN;
    float s = b2[c];
    #pragma unroll
    for (int h = 0; h < HID; h++) s += b1[h] * W2[h*LEN + c];
    g_bc[c] = s;
  } else if (i < LEN*LEN + LEN + NB*LEN){
    g_pool[i - (LEN*LEN + LEN)] = f2o(NEG_FILL);
  } else if (i < LEN*LEN + LEN + NB*LEN + NB){
    g_cnt[i - (LEN*LEN + LEN + NB*LEN)] = 0u;
  }
}

/* ---- fused GEMM(tf32) + bias + LN + ReLU + mask + store + pool + broadcast ---- */
__global__ void __launch_bounds__(NTHREADS,1)
mlp_kernel(const float* __restrict__ X, const void* __restrict__ maskp,
           const float* __restrict__ gamma, const float* __restrict__ beta,
           float* __restrict__ out)
{
  extern __shared__ float sm[];
  float* Wp    = sm + SM_W;
  float* sGam  = sm + SM_CG;
  float* sBet  = sm + SM_CB;
  float* sBia  = sm + SM_CC;
  float* stats = sm + SM_ST;
  int*   sFlag = (int*)(sm + SM_FLAG);

  const int tid  = threadIdx.x;
  const int lane = tid & 31;
  const int wid  = tid >> 5;
  const int g    = lane >> 2, tig = lane & 3;
  const int wm   = wid >> 2,  wn  = wid & 3;   /* 4 m-warps x 4 n-warps */
  const int cbase = wn*32;

  for (int i = tid; i < WP_FLOATS; i += NTHREADS) Wp[i] = g_Wp[i];
  if (tid < 128){
    sGam[tid] = gamma[tid];
    sBet[tid] = beta[tid];
    sBia[tid] = g_bc[tid];
  }

  const bool mu8 = (g_mask_u8 != 0);
  const unsigned char* m8  = (const unsigned char*)maskp;
  const int*           m32 = (const int*)maskp;

  const int per = (NTILES + gridDim.x - 1) / gridDim.x;
  const int tb  = blockIdx.x * per;
  const int te  = (tb + per < NTILES) ? tb + per : NTILES;
  if (tb >= te) return;

  float pm[8];
  #pragma unroll
  for (int i = 0; i < 8; i++) pm[i] = NEG_FILL;

  /* prefetch first tile into buf0 (plane-packed) */
  stage_tile(sm + SM_X0, X + (size_t)tb * TILE_M * LEN, tid);
  asm volatile("cp.async.commit_group;\n" ::: "memory");

  int segcnt = 0;
  for (int t = tb; t < te; t++){
    const int cur = (t - tb) & 1;
    if (t + 1 < te)
      stage_tile(sm + (cur ? SM_X0 : SM_X1), X + (size_t)(t+1) * TILE_M * LEN, tid);
    asm volatile("cp.async.commit_group;\n" ::: "memory");
    asm volatile("cp.async.wait_group 1;\n" ::: "memory");
    __syncthreads();                                  /* (A) cur tile ready */

    const float* Xs = sm + (cur ? SM_X1 : SM_X0);

    float acc[2][4][4];
    #pragma unroll
    for (int mt = 0; mt < 2; mt++)
      #pragma unroll
      for (int nt = 0; nt < 4; nt++)
        #pragma unroll
        for (int j = 0; j < 4; j++) acc[mt][nt][j] = 0.f;

    #pragma unroll
    for (int kk2 = 0; kk2 < 8; kk2++){
      /* A: 4 rows (wm*32 + {0,8,16,24} + g), plane tig, conflict-free LDS.128 */
      float4 rg4[4];
      #pragma unroll
      for (int mr = 0; mr < 4; mr++)
        rg4[mr] = *(const float4*)&Xs[tig*PXT + (wm*32 + mr*8 + g)*XJ + kk2*4];
      float4 w4[4];
      #pragma unroll
      for (int nt = 0; nt < 4; nt++)
        w4[nt] = *(const float4*)&Wp[tig*PST + (cbase + nt*8 + g)*CST + kk2*4];
      #pragma unroll
      for (int nt = 0; nt < 4; nt++){
        /* half0: k=16kk2+{tig,tig+4} -> .x/.y ; half1: +8 -> .z/.w (raw bits = tf32 trunc) */
        mma8(acc[0][nt], __float_as_uint(rg4[0].x), __float_as_uint(rg4[1].x),
                         __float_as_uint(rg4[0].y), __float_as_uint(rg4[1].y),
                         __float_as_uint(w4[nt].x), __float_as_uint(w4[nt].y));
        mma8(acc[1][nt], __float_as_uint(rg4[2].x), __float_as_uint(rg4[3].x),
                         __float_as_uint(rg4[2].y), __float_as_uint(rg4[3].y),
                         __float_as_uint(w4[nt].x), __float_as_uint(w4[nt].y));
        mma8(acc[0][nt], __float_as_uint(rg4[0].z), __float_as_uint(rg4[1].z),
                         __float_as_uint(rg4[0].w), __float_as_uint(rg4[1].w),
                         __float_as_uint(w4[nt].z), __float_as_uint(w4[nt].w));
        mma8(acc[1][nt], __float_as_uint(rg4[2].z), __float_as_uint(rg4[3].z),
                         __float_as_uint(rg4[2].w), __float_as_uint(rg4[3].w),
                         __float_as_uint(w4[nt].z), __float_as_uint(w4[nt].w));
      }
    }

    /* bias + LN partial stats */
    #pragma unroll
    for (int mt = 0; mt < 2; mt++){
      float s0=0.f, q0=0.f, s1=0.f, q1=0.f;
      #pragma unroll
      for (int nt = 0; nt < 4; nt++){
        float2 bb = *(const float2*)&sBia[cbase + nt*8 + 2*tig];
        float* a = acc[mt][nt];
        a[0]+=bb.x; a[1]+=bb.y; a[2]+=bb.x; a[3]+=bb.y;
        s0 += a[0]+a[1]; q0 += a[0]*a[0]+a[1]*a[1];
        s1 += a[2]+a[3]; q1 += a[2]*a[2]+a[3]*a[3];
      }
      #pragma unroll
      for (int off = 1; off < 4; off <<= 1){
        s0 += __shfl_xor_sync(0xffffffffu, s0, off);
        q0 += __shfl_xor_sync(0xffffffffu, q0, off);
        s1 += __shfl_xor_sync(0xffffffffu, s1, off);
        q1 += __shfl_xor_sync(0xffffffffu, q1, off);
      }
      if (tig == 0){
        int rb = wm*32 + mt*16;
        stats[(rb+g  )*8 + wn]     = s0;
        stats[(rb+g  )*8 + 4 + wn] = q0;
        stats[(rb+g+8)*8 + wn]     = s1;
        stats[(rb+g+8)*8 + 4 + wn] = q1;
      }
    }
    __syncthreads();                                  /* (B) stats ready */

    const size_t growbase = (size_t)t * TILE_M;
    #pragma unroll
    for (int mt = 0; mt < 2; mt++){
      const int rb = wm*32 + mt*16;
      const int rg = rb + g, rg8 = rb + g + 8;
      float4 su4a = *(const float4*)&stats[rg *8];
      float4 sq4a = *(const float4*)&stats[rg *8 + 4];
      float4 su4b = *(const float4*)&stats[rg8*8];
      float4 sq4b = *(const float4*)&stats[rg8*8 + 4];
      float sua = su4a.x+su4a.y+su4a.z+su4a.w, sqa = sq4a.x+sq4a.y+sq4a.z+sq4a.w;
      float sub = su4b.x+su4b.y+su4b.z+su4b.w, sqb = sq4b.x+sq4b.y+sq4b.z+sq4b.w;
      float mua = sua * (1.0f/LEN), mub = sub * (1.0f/LEN);
      float rsa = rsqrtf(fmaxf(sqa*(1.0f/LEN) - mua*mua, 0.f) + LN_EPS);
      float rsb = rsqrtf(fmaxf(sqb*(1.0f/LEN) - mub*mub, 0.f) + LN_EPS);
      bool mka = mu8 ? (m8[growbase+rg ] != 0) : (m32[growbase+rg ] != 0);
      bool mkb = mu8 ? (m8[growbase+rg8] != 0) : (m32[growbase+rg8] != 0);
      float* orowa = out + (growbase + rg ) * (2*LEN);
      float* orowb = out + (growbase + rg8) * (2*LEN);
      #pragma unroll
      for (int nt = 0; nt < 4; nt++){
        const int c0 = cbase + nt*8 + 2*tig;
        float2 gg = *(const float2*)&sGam[c0];
        float2 be = *(const float2*)&sBet[c0];
        float* a = acc[mt][nt];
        float v0 = (a[0]-mua)*rsa*gg.x + be.x;
        float v1 = (a[1]-mua)*rsa*gg.y + be.y;
        float v2 = (a[2]-mub)*rsb*gg.x + be.x;
        float v3 = (a[3]-mub)*rsb*gg.y + be.y;
        v0 = mka ? fmaxf(v0, 0.f) : NEG_FILL;
        v1 = mka ? fmaxf(v1, 0.f) : NEG_FILL;
        v2 = mkb ? fmaxf(v2, 0.f) : NEG_FILL;
        v3 = mkb ? fmaxf(v3, 0.f) : NEG_FILL;
        __stcs((float2*)(orowa + c0), make_float2(v0, v1));
        __stcs((float2*)(orowb + c0), make_float2(v2, v3));
        pm[2*nt]   = fmaxf(pm[2*nt],   fmaxf(v0, v2));
        pm[2*nt+1] = fmaxf(pm[2*nt+1], fmaxf(v1, v3));
      }
    }
    segcnt++;

    /* batch boundary: flush pool, count tiles, last finisher broadcasts */
    if (t == te-1 || ((t+1) >> 4) != (t >> 4)){
      const int b = t >> 4;
      #pragma unroll
      for (int i = 0; i < 8; i++){
        pm[i] = fmaxf(pm[i], __shfl_xor_sync(0xffffffffu, pm[i], 4));
        pm[i] = fmaxf(pm[i], __shfl_xor_sync(0xffffffffu, pm[i], 8));
        pm[i] = fmaxf(pm[i], __shfl_xor_sync(0xffffffffu, pm[i], 16));
      }
      if (lane < 4){   /* g==0 lanes: tig = lane */
        unsigned* pp = g_pool + b*LEN;
        #pragma unroll
        for (int nt = 0; nt < 4; nt++){
          int c0 = cbase + nt*8 + 2*lane;
          atomicMax(pp + c0,     f2o(pm[2*nt]));
          atomicMax(pp + c0 + 1, f2o(pm[2*nt+1]));
        }
      }
      __threadfence();
      __syncthreads();
      if (tid == 0){
        unsigned old = atomicAdd(&g_cnt[b], (unsigned)segcnt);
        *sFlag = (old + (unsigned)segcnt == 16u) ? 1 : 0;
      }
      __syncthreads();
      if (*sFlag){
        /* this CTA completed batch b: broadcast pooled max into second halves */
        uint4 p = __ldcg((const uint4*)(g_pool + b*LEN + lane*4));
        float4 v = make_float4(o2f(p.x), o2f(p.y), o2f(p.z), o2f(p.w));
        float* wb = out + (size_t)b*NN*(2*LEN) + LEN + lane*4
                        + (size_t)wid*128*(2*LEN);
        #pragma unroll 8
        for (int r = 0; r < 128; r++)
          __stcs((float4*)(wb + (size_t)r*(2*LEN)), v);
      }
      #pragma unroll
      for (int i = 0; i < 8; i++) pm[i] = NEG_FILL;
      segcnt = 0;
    }
  }
}

extern "C" void kernel_launch(void* const* d_in, const int* in_sizes, int n_in,
                              void* d_out, int out_size){
  (void)in_sizes; (void)n_in; (void)out_size;
  const float* X    = (const float*)d_in[0];
  const void*  mask = d_in[1];
  const float* W1   = (const float*)d_in[2];
  const float* b1   = (const float*)d_in[3];
  const float* W2   = (const float*)d_in[4];
  const float* b2   = (const float*)d_in[5];
  const float* gm   = (const float*)d_in[6];
  const float* bt   = (const float*)d_in[7];
  float* out = (float*)d_out;

  cudaFuncSetAttribute(mlp_kernel, cudaFuncAttributeMaxDynamicSharedMemorySize, SMEM_BYTES);

  int dev = 0; cudaGetDevice(&dev);
  int sms = 148;
  cudaDeviceGetAttribute(&sms, cudaDevAttrMultiProcessorCount, dev);
  if (sms <= 0) sms = 148;

  prep_kernel<<<(LEN*LEN + LEN + NB*LEN + NB + 255)/256, 256>>>(W1, b1, W2, b2,
                                                                (const unsigned*)mask);
  mlp_kernel<<<sms, NTHREADS, SMEM_BYTES>>>(X, mask, gm, bt, out);
}

// round 8
// speedup vs baseline: 1.3137x; 1.3137x over previous
#include <cuda_runtime.h>
#include <cstdint>
#include <cstddef>

#define LEN 128
#define HID 64
#define NB 256
#define NN 2048
#define NROWS (NB*NN)          /* 524288 */
#define TILE_M 128
#define NTILES (NROWS/TILE_M)  /* 4096, 16 tiles per batch */
#define NEG_FILL -1.0e9f
#define LN_EPS 1e-3f

/* W plane-packed layout: Wp[p][c][j] = W[4j+p][c], p=k%4, j=k/4 */
#define CST 36                 /* col stride (floats), mod32=4, 16B-mult */
#define PST (128*CST + 8)      /* 4616 plane stride, mod32=8, 16B-mult */
#define WP_FLOATS (4*PST)      /* 18464 */
#define XST 132                /* X tile row stride (floats), mod32=4 */
#define XTILE (TILE_M*XST)     /* 16896 */

#define SM_X0 WP_FLOATS
#define SM_X1 (SM_X0 + XTILE)
#define SM_ST (SM_X1 + XTILE)
#define SM_FLAG (SM_ST + TILE_M*8)
#define SM_FLOATS (SM_FLAG + 4)
#define SMEM_BYTES (SM_FLOATS*4)   /* ~213 KB */

__device__ float    g_Wp[WP_FLOATS];   /* combined W1@W2, tf32-rounded, plane-packed */
__device__ float    g_bc[LEN];         /* combined bias b1@W2 + b2 */
__device__ unsigned g_pool[NB*LEN];    /* per-(batch,channel) max, ordered-uint */
__device__ unsigned g_cnt[NB];         /* per-batch completed-tile counters */
__device__ int      g_mask_u8;

__device__ __forceinline__ unsigned f2o(float f){
  unsigned u = __float_as_uint(f);
  return (u & 0x80000000u) ? ~u : (u | 0x80000000u);
}
__device__ __forceinline__ float o2f(unsigned o){
  unsigned u = (o & 0x80000000u) ? (o & 0x7fffffffu) : ~o;
  return __uint_as_float(u);
}
__device__ __forceinline__ unsigned tf32r(float x){
  unsigned r; asm("cvt.rna.tf32.f32 %0, %1;" : "=r"(r) : "f"(x)); return r;
}
__device__ __forceinline__ void mma8(float* c, const unsigned* a, const unsigned* b){
  asm volatile(
    "mma.sync.aligned.m16n8k8.row.col.f32.tf32.tf32.f32 "
    "{%0,%1,%2,%3}, {%4,%5,%6,%7}, {%8,%9}, {%0,%1,%2,%3};\n"
    : "+f"(c[0]), "+f"(c[1]), "+f"(c[2]), "+f"(c[3])
    : "r"(a[0]), "r"(a[1]), "r"(a[2]), "r"(a[3]), "r"(b[0]), "r"(b[1]));
}
__device__ __forceinline__ void cpa16(float* s, const float* g){
  unsigned sa = (unsigned)__cvta_generic_to_shared(s);
  asm volatile("cp.async.cg.shared.global [%0], [%1], 16;\n" :: "r"(sa), "l"(g));
}

/* ---- prep: combined weight (plane layout) + bias + pool/counter init + mask probe ---- */
__global__ void prep_kernel(const float* __restrict__ W1, const float* __restrict__ b1,
                            const float* __restrict__ W2, const float* __restrict__ b2,
                            const unsigned* __restrict__ mw){
  if (blockIdx.x == 0){
    __shared__ int flag;
    if (threadIdx.x == 0) flag = 0;
    __syncthreads();
    int loc = 0;
    #pragma unroll
    for (int k = 0; k < 4; k++)
      if (mw[threadIdx.x*4 + k] > 1u) loc = 1;   /* u8-packed bools -> words >1 */
    if (loc) flag = 1;
    __syncthreads();
    if (threadIdx.x == 0) g_mask_u8 = flag;
  }
  int i = blockIdx.x*blockDim.x + threadIdx.x;
  if (i < LEN*LEN){
    int k = i >> 7, c = i & 127;
    float s = 0.f;
    #pragma unroll
    for (int h = 0; h < HID; h++) s += W1[k*HID + h] * W2[h*LEN + c];
    g_Wp[(k&3)*PST + c*CST + (k>>2)] = __uint_as_float(tf32r(s));
  } else if (i < LEN*LEN + LEN){
    int c = i - LEN*LEN;
    float s = b2[c];
    #pragma unroll
    for (int h = 0; h < HID; h++) s += b1[h] * W2[h*LEN + c];
    g_bc[c] = s;
  } else if (i < LEN*LEN + LEN + NB*LEN){
    g_pool[i - (LEN*LEN + LEN)] = f2o(NEG_FILL);
  } else if (i < LEN*LEN + LEN + NB*LEN + NB){
    g_cnt[i - (LEN*LEN + LEN + NB*LEN)] = 0u;
  }
}

/* ---- fused GEMM(tf32) + bias + LN + ReLU + mask + store + pool + broadcast ---- */
__global__ void __launch_bounds__(512,1)
mlp_kernel(const float* __restrict__ X, const void* __restrict__ maskp,
           const float* __restrict__ gamma, const float* __restrict__ beta,
           float* __restrict__ out)
{
  extern __shared__ float sm[];
  float* Wp    = sm;
  float* stats = sm + SM_ST;
  int*   sFlag = (int*)(sm + SM_FLAG);

  const int tid  = threadIdx.x;
  const int lane = tid & 31;
  const int wid  = tid >> 5;
  const int g    = lane >> 2, tig = lane & 3;
  const int wm   = wid >> 2,  wn  = wid & 3;   /* 4 m-warps x 4 n-warps */
  const int cbase = wn*32;

  for (int i = tid; i < WP_FLOATS; i += 512) Wp[i] = g_Wp[i];

  float gam[8], bet[8], bia[8];
  #pragma unroll
  for (int nt = 0; nt < 4; nt++){
    int c0 = cbase + nt*8 + 2*tig;
    gam[2*nt] = gamma[c0]; gam[2*nt+1] = gamma[c0+1];
    bet[2*nt] = beta[c0];  bet[2*nt+1] = beta[c0+1];
    bia[2*nt] = g_bc[c0];  bia[2*nt+1] = g_bc[c0+1];
  }
  const bool mu8 = (g_mask_u8 != 0);
  const unsigned char* m8  = (const unsigned char*)maskp;
  const int*           m32 = (const int*)maskp;

  const int per = (NTILES + gridDim.x - 1) / gridDim.x;
  const int tb  = blockIdx.x * per;
  const int te  = (tb + per < NTILES) ? tb + per : NTILES;
  if (tb >= te) return;

  float pm[8];
  #pragma unroll
  for (int i = 0; i < 8; i++) pm[i] = NEG_FILL;

  /* prefetch first tile into buf0 */
  {
    const float* src = X + (size_t)tb * TILE_M * LEN;
    float* dst = sm + SM_X0;
    #pragma unroll
    for (int c = tid; c < TILE_M*32; c += 512){
      int r = c >> 5, q = c & 31;
      cpa16(dst + r*XST + q*4, src + (size_t)r*LEN + q*4);
    }
  }
  asm volatile("cp.async.commit_group;\n" ::: "memory");

  int segcnt = 0;
  for (int t = tb; t < te; t++){
    const int cur = (t - tb) & 1;
    if (t + 1 < te){
      const float* src = X + (size_t)(t+1) * TILE_M * LEN;
      float* dst = sm + (cur ? SM_X0 : SM_X1);
      #pragma unroll
      for (int c = tid; c < TILE_M*32; c += 512){
        int r = c >> 5, q = c & 31;
        cpa16(dst + r*XST + q*4, src + (size_t)r*LEN + q*4);
      }
    }
    asm volatile("cp.async.commit_group;\n" ::: "memory");
    asm volatile("cp.async.wait_group 1;\n" ::: "memory");
    __syncthreads();                                  /* (A) cur tile ready */

    const float* Xs = sm + (cur ? SM_X1 : SM_X0);

    float acc[2][4][4];
    #pragma unroll
    for (int mt = 0; mt < 2; mt++)
      #pragma unroll
      for (int nt = 0; nt < 4; nt++)
        #pragma unroll
        for (int j = 0; j < 4; j++) acc[mt][nt][j] = 0.f;

    #pragma unroll
    for (int kk2 = 0; kk2 < 8; kk2++){
      float4 w4[4];
      #pragma unroll
      for (int nt = 0; nt < 4; nt++)
        w4[nt] = *(const float4*)&Wp[tig*PST + (cbase + nt*8 + g)*CST + kk2*4];
      #pragma unroll
      for (int half = 0; half < 2; half++){
        const int k0 = kk2*16 + half*8;
        unsigned af[2][4];
        #pragma unroll
        for (int mt = 0; mt < 2; mt++){
          int rb = wm*32 + mt*16;
          af[mt][0] = __float_as_uint(Xs[(rb+g  )*XST + k0+tig  ]);  /* raw bits: tf32 trunc */
          af[mt][1] = __float_as_uint(Xs[(rb+g+8)*XST + k0+tig  ]);
          af[mt][2] = __float_as_uint(Xs[(rb+g  )*XST + k0+tig+4]);
          af[mt][3] = __float_as_uint(Xs[(rb+g+8)*XST + k0+tig+4]);
        }
        unsigned bf[4][2];
        #pragma unroll
        for (int nt = 0; nt < 4; nt++){
          bf[nt][0] = half ? __float_as_uint(w4[nt].z) : __float_as_uint(w4[nt].x);
          bf[nt][1] = half ? __float_as_uint(w4[nt].w) : __float_as_uint(w4[nt].y);
        }
        #pragma unroll
        for (int mt = 0; mt < 2; mt++)
          #pragma unroll
          for (int nt = 0; nt < 4; nt++)
            mma8(acc[mt][nt], af[mt], bf[nt]);
      }
    }

    /* bias + LN partial stats */
    #pragma unroll
    for (int mt = 0; mt < 2; mt++){
      float s0=0.f, q0=0.f, s1=0.f, q1=0.f;
      #pragma unroll
      for (int nt = 0; nt < 4; nt++){
        float* a = acc[mt][nt];
        a[0]+=bia[2*nt]; a[1]+=bia[2*nt+1]; a[2]+=bia[2*nt]; a[3]+=bia[2*nt+1];
        s0 += a[0]+a[1]; q0 += a[0]*a[0]+a[1]*a[1];
        s1 += a[2]+a[3]; q1 += a[2]*a[2]+a[3]*a[3];
      }
      #pragma unroll
      for (int off = 1; off < 4; off <<= 1){
        s0 += __shfl_xor_sync(0xffffffffu, s0, off);
        q0 += __shfl_xor_sync(0xffffffffu, q0, off);
        s1 += __shfl_xor_sync(0xffffffffu, s1, off);
        q1 += __shfl_xor_sync(0xffffffffu, q1, off);
      }
      if (tig == 0){
        int rb = wm*32 + mt*16;
        stats[(rb+g  )*8 + wn]     = s0;
        stats[(rb+g  )*8 + 4 + wn] = q0;
        stats[(rb+g+8)*8 + wn]     = s1;
        stats[(rb+g+8)*8 + 4 + wn] = q1;
      }
    }
    __syncthreads();                                  /* (B) stats ready; buffers safe */

    const size_t growbase = (size_t)t * TILE_M;
    #pragma unroll
    for (int mt = 0; mt < 2; mt++){
      const int rb = wm*32 + mt*16;
      const int rg = rb + g, rg8 = rb + g + 8;
      float4 su4a = *(const float4*)&stats[rg *8];
      float4 sq4a = *(const float4*)&stats[rg *8 + 4];
      float4 su4b = *(const float4*)&stats[rg8*8];
      float4 sq4b = *(const float4*)&stats[rg8*8 + 4];
      float sua = su4a.x+su4a.y+su4a.z+su4a.w, sqa = sq4a.x+sq4a.y+sq4a.z+sq4a.w;
      float sub = su4b.x+su4b.y+su4b.z+su4b.w, sqb = sq4b.x+sq4b.y+sq4b.z+sq4b.w;
      float mua = sua * (1.0f/LEN), mub = sub * (1.0f/LEN);
      float rsa = rsqrtf(fmaxf(sqa*(1.0f/LEN) - mua*mua, 0.f) + LN_EPS);
      float rsb = rsqrtf(fmaxf(sqb*(1.0f/LEN) - mub*mub, 0.f) + LN_EPS);
      bool mka = mu8 ? (m8[growbase+rg ] != 0) : (m32[growbase+rg ] != 0);
      bool mkb = mu8 ? (m8[growbase+rg8] != 0) : (m32[growbase+rg8] != 0);
      float* orowa = out + (growbase + rg ) * (2*LEN);
      float* orowb = out + (growbase + rg8) * (2*LEN);
      #pragma unroll
      for (int nt = 0; nt < 4; nt++){
        const int c0 = cbase + nt*8 + 2*tig;
        float* a = acc[mt][nt];
        float v0 = (a[0]-mua)*rsa*gam[2*nt]   + bet[2*nt];
        float v1 = (a[1]-mua)*rsa*gam[2*nt+1] + bet[2*nt+1];
        float v2 = (a[2]-mub)*rsb*gam[2*nt]   + bet[2*nt];
        float v3 = (a[3]-mub)*rsb*gam[2*nt+1] + bet[2*nt+1];
        v0 = mka ? fmaxf(v0, 0.f) : NEG_FILL;
        v1 = mka ? fmaxf(v1, 0.f) : NEG_FILL;
        v2 = mkb ? fmaxf(v2, 0.f) : NEG_FILL;
        v3 = mkb ? fmaxf(v3, 0.f) : NEG_FILL;
        __stcs((float2*)(orowa + c0), make_float2(v0, v1));
        __stcs((float2*)(orowb + c0), make_float2(v2, v3));
        pm[2*nt]   = fmaxf(pm[2*nt],   fmaxf(v0, v2));
        pm[2*nt+1] = fmaxf(pm[2*nt+1], fmaxf(v1, v3));
      }
    }
    segcnt++;

    /* batch boundary: flush pool, count tiles, last finisher broadcasts */
    if (t == te-1 || ((t+1) >> 4) != (t >> 4)){
      const int b = t >> 4;
      #pragma unroll
      for (int i = 0; i < 8; i++){
        pm[i] = fmaxf(pm[i], __shfl_xor_sync(0xffffffffu, pm[i], 4));
        pm[i] = fmaxf(pm[i], __shfl_xor_sync(0xffffffffu, pm[i], 8));
        pm[i] = fmaxf(pm[i], __shfl_xor_sync(0xffffffffu, pm[i], 16));
      }
      if (lane < 4){   /* g==0 lanes: tig = lane */
        unsigned* pp = g_pool + b*LEN;
        #pragma unroll
        for (int nt = 0; nt < 4; nt++){
          int c0 = cbase + nt*8 + 2*lane;
          atomicMax(pp + c0,     f2o(pm[2*nt]));
          atomicMax(pp + c0 + 1, f2o(pm[2*nt+1]));
        }
      }
      __threadfence();
      __syncthreads();
      if (tid == 0){
        unsigned old = atomicAdd(&g_cnt[b], (unsigned)segcnt);
        *sFlag = (old + (unsigned)segcnt == 16u) ? 1 : 0;
      }
      __syncthreads();
      if (*sFlag){
        /* this CTA completed batch b: broadcast pooled max into second halves.
           16 warps x 128 rows each; one warp covers a row's 128-col half. */
        uint4 p = __ldcg((const uint4*)(g_pool + b*LEN + lane*4));
        float4 v = make_float4(o2f(p.x), o2f(p.y), o2f(p.z), o2f(p.w));
        float* wb = out + (size_t)b*NN*(2*LEN) + LEN + lane*4
                        + (size_t)wid*128*(2*LEN);
        #pragma unroll 8
        for (int r = 0; r < 128; r++)
          __stcs((float4*)(wb + (size_t)r*(2*LEN)), v);
      }
      #pragma unroll
      for (int i = 0; i < 8; i++) pm[i] = NEG_FILL;
      segcnt = 0;
    }
  }
}

extern "C" void kernel_launch(void* const* d_in, const int* in_sizes, int n_in,
                              void* d_out, int out_size){
  (void)in_sizes; (void)n_in; (void)out_size;
  const float* X    = (const float*)d_in[0];
  const void*  mask = d_in[1];
  const float* W1   = (const float*)d_in[2];
  const float* b1   = (const float*)d_in[3];
  const float* W2   = (const float*)d_in[4];
  const float* b2   = (const float*)d_in[5];
  const float* gm   = (const float*)d_in[6];
  const float* bt   = (const float*)d_in[7];
  float* out = (float*)d_out;

  cudaFuncSetAttribute(mlp_kernel, cudaFuncAttributeMaxDynamicSharedMemorySize, SMEM_BYTES);

  int dev = 0; cudaGetDevice(&dev);
  int sms = 148;
  cudaDeviceGetAttribute(&sms, cudaDevAttrMultiProcessorCount, dev);
  if (sms <= 0) sms = 148;

  prep_kernel<<<(LEN*LEN + LEN + NB*LEN + NB + 255)/256, 256>>>(W1, b1, W2, b2,
                                                                (const unsigned*)mask);
  mlp_kernel<<<sms, 512, SMEM_BYTES>>>(X, mask, gm, bt, out);
}